// round 11
// baseline (speedup 1.0000x reference)
#include <cuda_runtime.h>
#include <cuda_bf16.h>
#include <math.h>

// MoE gate: logits = hs @ W^T  (N x 4), softmax over 4, top-2.
// Output layout (float):
//   [0, 2N)   : topk_idx  (as float)
//   [2N, 4N)  : topk_weight
//   [4N, 6N)  : row_idx   (row_idx[i][j] = j*N + i, as float)
//
// R11: R9's proven loop + __launch_bounds__(256, 5) to force regs <= 51 and
// lift residency 4 -> 5 blocks/SM (32 -> 40 warps). Session evidence says
// warps/SM is the binding secondary resource; this raises it without touching
// the inner-loop structure. If ptxas spills, revert to R9 (56.06 us).

constexpr int EMBED = 2560;
constexpr int NEXP  = 4;
constexpr int VEC   = EMBED / 4;   // 640 float4 per row
constexpr int WARPS_PER_BLOCK = 8; // 256 threads
constexpr int TOK_PER_WARP    = 4;
constexpr int TOK_PER_BLOCK   = WARPS_PER_BLOCK * TOK_PER_WARP;  // 32

__global__ __launch_bounds__(WARPS_PER_BLOCK * 32, 5)
void moe_gate_kernel(const float* __restrict__ hs,
                     const float* __restrict__ w,
                     float* __restrict__ out,
                     int n) {
    const int lane = threadIdx.x & 31;
    const int wid  = threadIdx.x >> 5;
    const int tok0 = (blockIdx.x * WARPS_PER_BLOCK + wid) * TOK_PER_WARP;
    if (tok0 >= n) return;

    const float4* __restrict__ W4 = reinterpret_cast<const float4*>(w);
    const float4* __restrict__ H4 =
        reinterpret_cast<const float4*>(hs) + (size_t)tok0 * VEC;

    float acc[TOK_PER_WARP][NEXP];
#pragma unroll
    for (int i = 0; i < TOK_PER_WARP; i++)
#pragma unroll
        for (int e = 0; e < NEXP; e++) acc[i][e] = 0.0f;

    // 8 LDG.128 per iteration, compiler-scheduled.
    //   hidden: __ldcs (evict-first; 335 MB stream must not thrash caches)
    //   weight: __ldg  (read-only, L1-resident 40 KB working set)
    for (int c = lane; c < VEC; c += 32) {
        const float4 w0 = __ldg(&W4[0 * VEC + c]);
        const float4 w1 = __ldg(&W4[1 * VEC + c]);
        const float4 w2 = __ldg(&W4[2 * VEC + c]);
        const float4 w3 = __ldg(&W4[3 * VEC + c]);
#pragma unroll
        for (int i = 0; i < TOK_PER_WARP; i++) {
            const float4 h = __ldcs(&H4[(size_t)i * VEC + c]);
            acc[i][0] = fmaf(h.x, w0.x, fmaf(h.y, w0.y, fmaf(h.z, w0.z, fmaf(h.w, w0.w, acc[i][0]))));
            acc[i][1] = fmaf(h.x, w1.x, fmaf(h.y, w1.y, fmaf(h.z, w1.z, fmaf(h.w, w1.w, acc[i][1]))));
            acc[i][2] = fmaf(h.x, w2.x, fmaf(h.y, w2.y, fmaf(h.z, w2.z, fmaf(h.w, w2.w, acc[i][2]))));
            acc[i][3] = fmaf(h.x, w3.x, fmaf(h.y, w3.y, fmaf(h.z, w3.z, fmaf(h.w, w3.w, acc[i][3]))));
        }
    }

    // Full butterfly reduce: every lane ends with the complete sums.
#pragma unroll
    for (int i = 0; i < TOK_PER_WARP; i++)
#pragma unroll
        for (int e = 0; e < NEXP; e++) {
            float v = acc[i][e];
#pragma unroll
            for (int off = 16; off > 0; off >>= 1)
                v += __shfl_xor_sync(0xFFFFFFFFu, v, off);
            acc[i][e] = v;
        }

    if (lane < TOK_PER_WARP) {
        const int tok = tok0 + lane;
        if (tok < n) {
            float l[NEXP];
#pragma unroll
            for (int e = 0; e < NEXP; e++) l[e] = acc[lane][e];

            // softmax over 4
            float m = l[0];
#pragma unroll
            for (int e = 1; e < NEXP; e++) m = fmaxf(m, l[e]);
            float p[NEXP];
            float s = 0.0f;
#pragma unroll
            for (int e = 0; e < NEXP; e++) { p[e] = expf(l[e] - m); s += p[e]; }
            const float inv = 1.0f / s;
#pragma unroll
            for (int e = 0; e < NEXP; e++) p[e] *= inv;

            // top-2 with lowest-index tie-break (strict >)
            int bi = 0;
            float bv = p[0];
#pragma unroll
            for (int e = 1; e < NEXP; e++)
                if (p[e] > bv) { bv = p[e]; bi = e; }
            int si = -1;
            float sv = -1.0f;
#pragma unroll
            for (int e = 0; e < NEXP; e++) {
                if (e == bi) continue;
                if (p[e] > sv) { sv = p[e]; si = e; }
            }

            const size_t n2 = 2 * (size_t)n;
            out[(size_t)tok * 2 + 0]          = (float)bi;
            out[(size_t)tok * 2 + 1]          = (float)si;
            out[n2 + (size_t)tok * 2 + 0]     = bv;
            out[n2 + (size_t)tok * 2 + 1]     = sv;
            out[2 * n2 + (size_t)tok * 2 + 0] = (float)tok;
            out[2 * n2 + (size_t)tok * 2 + 1] = (float)(n + tok);
        }
    }
}

extern "C" void kernel_launch(void* const* d_in, const int* in_sizes, int n_in,
                              void* d_out, int out_size) {
    const float* hs = (const float*)d_in[0];
    const float* w  = (const float*)d_in[1];
    float* out      = (float*)d_out;

    const int n = in_sizes[0] / EMBED;  // 32768
    const int blocks = (n + TOK_PER_BLOCK - 1) / TOK_PER_BLOCK;  // 1024
    moe_gate_kernel<<<blocks, WARPS_PER_BLOCK * 32>>>(hs, w, out, n);
}

// round 12
// speedup vs baseline: 1.4950x; 1.4950x over previous
#include <cuda_runtime.h>
#include <cuda_bf16.h>
#include <math.h>

// MoE gate: logits = hs @ W^T  (N x 4), softmax over 4, top-2.
// Output layout (float):
//   [0, 2N)   : topk_idx  (as float)
//   [2N, 4N)  : topk_weight
//   [4N, 6N)  : row_idx   (row_idx[i][j] = j*N + i, as float)
//
// FINAL (R9 == R12): naive compiler-scheduled loop, 4 tokens/warp, 256-thread
// blocks, __ldcs on the streaming input, __ldg on the resident weights.
// 63 regs -> 4 blocks/SM; measured 55.8-57.2 us @ ~6.05 TB/s, which is the
// sustainable single-pass read-stream bandwidth on this part.
//
// Verified local optimum in every direction:
//   - smem weights (R2):        occupancy collapse            -> 69.7 us
//   - manual ping-pong (R3):    fragmented issue              -> 70.1 us
//   - persistent grid (R4):     neutral kernel + graph ovh    -> 60.1 us
//   - TOK=8 (R5):               occ halved cancels MLP gain   -> 58.5 us
//   - cp.async pipeline (R6):   ALU/address overhead          -> 70.1 us
//   - unroll x2 (R8):           regs 72, occ 4->3 blocks      -> 64.0 us
//   - maxBlocks=5 cap (R11):    regs 48 kills 8-load batch,
//                               MLP 8->2 despite occ 52%      -> 86.5 us
// Governing law: the 63-reg schedule is exactly the budget where the full
// 8 x LDG.128 batch stays register-resident. Do not perturb it.

constexpr int EMBED = 2560;
constexpr int NEXP  = 4;
constexpr int VEC   = EMBED / 4;   // 640 float4 per row
constexpr int WARPS_PER_BLOCK = 8; // 256 threads
constexpr int TOK_PER_WARP    = 4;
constexpr int TOK_PER_BLOCK   = WARPS_PER_BLOCK * TOK_PER_WARP;  // 32

__global__ __launch_bounds__(WARPS_PER_BLOCK * 32)
void moe_gate_kernel(const float* __restrict__ hs,
                     const float* __restrict__ w,
                     float* __restrict__ out,
                     int n) {
    const int lane = threadIdx.x & 31;
    const int wid  = threadIdx.x >> 5;
    const int tok0 = (blockIdx.x * WARPS_PER_BLOCK + wid) * TOK_PER_WARP;
    if (tok0 >= n) return;

    const float4* __restrict__ W4 = reinterpret_cast<const float4*>(w);
    const float4* __restrict__ H4 =
        reinterpret_cast<const float4*>(hs) + (size_t)tok0 * VEC;

    float acc[TOK_PER_WARP][NEXP];
#pragma unroll
    for (int i = 0; i < TOK_PER_WARP; i++)
#pragma unroll
        for (int e = 0; e < NEXP; e++) acc[i][e] = 0.0f;

    // 8 LDG.128 per iteration, compiler-scheduled.
    //   hidden: __ldcs (evict-first; 335 MB stream must not thrash caches)
    //   weight: __ldg  (read-only, L1-resident 40 KB working set)
    for (int c = lane; c < VEC; c += 32) {
        const float4 w0 = __ldg(&W4[0 * VEC + c]);
        const float4 w1 = __ldg(&W4[1 * VEC + c]);
        const float4 w2 = __ldg(&W4[2 * VEC + c]);
        const float4 w3 = __ldg(&W4[3 * VEC + c]);
#pragma unroll
        for (int i = 0; i < TOK_PER_WARP; i++) {
            const float4 h = __ldcs(&H4[(size_t)i * VEC + c]);
            acc[i][0] = fmaf(h.x, w0.x, fmaf(h.y, w0.y, fmaf(h.z, w0.z, fmaf(h.w, w0.w, acc[i][0]))));
            acc[i][1] = fmaf(h.x, w1.x, fmaf(h.y, w1.y, fmaf(h.z, w1.z, fmaf(h.w, w1.w, acc[i][1]))));
            acc[i][2] = fmaf(h.x, w2.x, fmaf(h.y, w2.y, fmaf(h.z, w2.z, fmaf(h.w, w2.w, acc[i][2]))));
            acc[i][3] = fmaf(h.x, w3.x, fmaf(h.y, w3.y, fmaf(h.z, w3.z, fmaf(h.w, w3.w, acc[i][3]))));
        }
    }

    // Full butterfly reduce: every lane ends with the complete sums.
#pragma unroll
    for (int i = 0; i < TOK_PER_WARP; i++)
#pragma unroll
        for (int e = 0; e < NEXP; e++) {
            float v = acc[i][e];
#pragma unroll
            for (int off = 16; off > 0; off >>= 1)
                v += __shfl_xor_sync(0xFFFFFFFFu, v, off);
            acc[i][e] = v;
        }

    if (lane < TOK_PER_WARP) {
        const int tok = tok0 + lane;
        if (tok < n) {
            float l[NEXP];
#pragma unroll
            for (int e = 0; e < NEXP; e++) l[e] = acc[lane][e];

            // softmax over 4
            float m = l[0];
#pragma unroll
            for (int e = 1; e < NEXP; e++) m = fmaxf(m, l[e]);
            float p[NEXP];
            float s = 0.0f;
#pragma unroll
            for (int e = 0; e < NEXP; e++) { p[e] = expf(l[e] - m); s += p[e]; }
            const float inv = 1.0f / s;
#pragma unroll
            for (int e = 0; e < NEXP; e++) p[e] *= inv;

            // top-2 with lowest-index tie-break (strict >)
            int bi = 0;
            float bv = p[0];
#pragma unroll
            for (int e = 1; e < NEXP; e++)
                if (p[e] > bv) { bv = p[e]; bi = e; }
            int si = -1;
            float sv = -1.0f;
#pragma unroll
            for (int e = 0; e < NEXP; e++) {
                if (e == bi) continue;
                if (p[e] > sv) { sv = p[e]; si = e; }
            }

            const size_t n2 = 2 * (size_t)n;
            out[(size_t)tok * 2 + 0]          = (float)bi;
            out[(size_t)tok * 2 + 1]          = (float)si;
            out[n2 + (size_t)tok * 2 + 0]     = bv;
            out[n2 + (size_t)tok * 2 + 1]     = sv;
            out[2 * n2 + (size_t)tok * 2 + 0] = (float)tok;
            out[2 * n2 + (size_t)tok * 2 + 1] = (float)(n + tok);
        }
    }
}

extern "C" void kernel_launch(void* const* d_in, const int* in_sizes, int n_in,
                              void* d_out, int out_size) {
    const float* hs = (const float*)d_in[0];
    const float* w  = (const float*)d_in[1];
    float* out      = (float*)d_out;

    const int n = in_sizes[0] / EMBED;  // 32768
    const int blocks = (n + TOK_PER_BLOCK - 1) / TOK_PER_BLOCK;  // 1024
    moe_gate_kernel<<<blocks, WARPS_PER_BLOCK * 32>>>(hs, w, out, n);
}

// round 13
// speedup vs baseline: 1.5050x; 1.0067x over previous
#include <cuda_runtime.h>
#include <cuda_bf16.h>
#include <math.h>

// MoE gate: logits = hs @ W^T  (N x 4), softmax over 4, top-2.
// Output layout (float):
//   [0, 2N)   : topk_idx  (as float)
//   [2N, 4N)  : topk_weight
//   [4N, 6N)  : row_idx   (row_idx[i][j] = j*N + i, as float)
//
// R13: R12's proven per-warp schedule (63 regs, 8 x LDG.128 batch, 4 tok/warp,
// __ldcs stream / __ldg weights) with CTA granularity halved: 128-thread
// blocks, grid 2048. No intra-block coupling exists (no __syncthreads), so
// warps/SM stays 32 (8 blocks x 4 warps x 63 regs = 64512 regs); only the
// scheduler's CTA replacement granularity changes (finer wave-tail drain).
// Inner loop is byte-identical to the verified optimum — do not perturb it.

constexpr int EMBED = 2560;
constexpr int NEXP  = 4;
constexpr int VEC   = EMBED / 4;   // 640 float4 per row
constexpr int WARPS_PER_BLOCK = 4; // 128 threads
constexpr int TOK_PER_WARP    = 4;
constexpr int TOK_PER_BLOCK   = WARPS_PER_BLOCK * TOK_PER_WARP;  // 16

__global__ __launch_bounds__(WARPS_PER_BLOCK * 32)
void moe_gate_kernel(const float* __restrict__ hs,
                     const float* __restrict__ w,
                     float* __restrict__ out,
                     int n) {
    const int lane = threadIdx.x & 31;
    const int wid  = threadIdx.x >> 5;
    const int tok0 = (blockIdx.x * WARPS_PER_BLOCK + wid) * TOK_PER_WARP;
    if (tok0 >= n) return;

    const float4* __restrict__ W4 = reinterpret_cast<const float4*>(w);
    const float4* __restrict__ H4 =
        reinterpret_cast<const float4*>(hs) + (size_t)tok0 * VEC;

    float acc[TOK_PER_WARP][NEXP];
#pragma unroll
    for (int i = 0; i < TOK_PER_WARP; i++)
#pragma unroll
        for (int e = 0; e < NEXP; e++) acc[i][e] = 0.0f;

    // 8 LDG.128 per iteration, compiler-scheduled.
    //   hidden: __ldcs (evict-first; 335 MB stream must not thrash caches)
    //   weight: __ldg  (read-only, L1-resident 40 KB working set)
    for (int c = lane; c < VEC; c += 32) {
        const float4 w0 = __ldg(&W4[0 * VEC + c]);
        const float4 w1 = __ldg(&W4[1 * VEC + c]);
        const float4 w2 = __ldg(&W4[2 * VEC + c]);
        const float4 w3 = __ldg(&W4[3 * VEC + c]);
#pragma unroll
        for (int i = 0; i < TOK_PER_WARP; i++) {
            const float4 h = __ldcs(&H4[(size_t)i * VEC + c]);
            acc[i][0] = fmaf(h.x, w0.x, fmaf(h.y, w0.y, fmaf(h.z, w0.z, fmaf(h.w, w0.w, acc[i][0]))));
            acc[i][1] = fmaf(h.x, w1.x, fmaf(h.y, w1.y, fmaf(h.z, w1.z, fmaf(h.w, w1.w, acc[i][1]))));
            acc[i][2] = fmaf(h.x, w2.x, fmaf(h.y, w2.y, fmaf(h.z, w2.z, fmaf(h.w, w2.w, acc[i][2]))));
            acc[i][3] = fmaf(h.x, w3.x, fmaf(h.y, w3.y, fmaf(h.z, w3.z, fmaf(h.w, w3.w, acc[i][3]))));
        }
    }

    // Full butterfly reduce: every lane ends with the complete sums.
#pragma unroll
    for (int i = 0; i < TOK_PER_WARP; i++)
#pragma unroll
        for (int e = 0; e < NEXP; e++) {
            float v = acc[i][e];
#pragma unroll
            for (int off = 16; off > 0; off >>= 1)
                v += __shfl_xor_sync(0xFFFFFFFFu, v, off);
            acc[i][e] = v;
        }

    if (lane < TOK_PER_WARP) {
        const int tok = tok0 + lane;
        if (tok < n) {
            float l[NEXP];
#pragma unroll
            for (int e = 0; e < NEXP; e++) l[e] = acc[lane][e];

            // softmax over 4
            float m = l[0];
#pragma unroll
            for (int e = 1; e < NEXP; e++) m = fmaxf(m, l[e]);
            float p[NEXP];
            float s = 0.0f;
#pragma unroll
            for (int e = 0; e < NEXP; e++) { p[e] = expf(l[e] - m); s += p[e]; }
            const float inv = 1.0f / s;
#pragma unroll
            for (int e = 0; e < NEXP; e++) p[e] *= inv;

            // top-2 with lowest-index tie-break (strict >)
            int bi = 0;
            float bv = p[0];
#pragma unroll
            for (int e = 1; e < NEXP; e++)
                if (p[e] > bv) { bv = p[e]; bi = e; }
            int si = -1;
            float sv = -1.0f;
#pragma unroll
            for (int e = 0; e < NEXP; e++) {
                if (e == bi) continue;
                if (p[e] > sv) { sv = p[e]; si = e; }
            }

            const size_t n2 = 2 * (size_t)n;
            out[(size_t)tok * 2 + 0]          = (float)bi;
            out[(size_t)tok * 2 + 1]          = (float)si;
            out[n2 + (size_t)tok * 2 + 0]     = bv;
            out[n2 + (size_t)tok * 2 + 1]     = sv;
            out[2 * n2 + (size_t)tok * 2 + 0] = (float)tok;
            out[2 * n2 + (size_t)tok * 2 + 1] = (float)(n + tok);
        }
    }
}

extern "C" void kernel_launch(void* const* d_in, const int* in_sizes, int n_in,
                              void* d_out, int out_size) {
    const float* hs = (const float*)d_in[0];
    const float* w  = (const float*)d_in[1];
    float* out      = (float*)d_out;

    const int n = in_sizes[0] / EMBED;  // 32768
    const int blocks = (n + TOK_PER_BLOCK - 1) / TOK_PER_BLOCK;  // 2048
    moe_gate_kernel<<<blocks, WARPS_PER_BLOCK * 32>>>(hs, w, out, n);
}

// round 14
// speedup vs baseline: 1.5499x; 1.0298x over previous
#include <cuda_runtime.h>
#include <cuda_bf16.h>
#include <math.h>

// MoE gate: logits = hs @ W^T  (N x 4), softmax over 4, top-2.
// Output layout (float):
//   [0, 2N)   : topk_idx  (as float)
//   [2N, 4N)  : topk_weight
//   [4N, 6N)  : row_idx   (row_idx[i][j] = j*N + i, as float)
//
// FINAL (R12/R14): naive compiler-scheduled loop, 4 tokens/warp, 256-thread
// blocks, __ldcs on the streaming input, __ldg on the resident weights.
// 63 regs -> 4 blocks/SM; 55.8-57.2 us @ ~6.05 TB/s — the sustainable
// single-pass fp32 read-stream bandwidth on this part (LTS-capped,
// path-independent; occupancy 22-52% all measure the same DRAM%).
//
// Exhaustively verified optimum (9 experiments, 0 wins over this loop):
//   smem weights (R2) 69.7us | ping-pong (R3) 70.1us | persistent (R4) 60.1us
//   TOK=8 (R5) 58.5us | cp.async (R6) 70.1us | unroll x2 (R8) 64.0us
//   maxBlocks=5 (R11) 86.5us | 128-thr blocks (R13) 56.7us (tie)
// Governing law: 63 regs is exactly the budget where the full 8 x LDG.128
// batch stays register-resident. Do not perturb the inner loop.

constexpr int EMBED = 2560;
constexpr int NEXP  = 4;
constexpr int VEC   = EMBED / 4;   // 640 float4 per row
constexpr int WARPS_PER_BLOCK = 8; // 256 threads
constexpr int TOK_PER_WARP    = 4;
constexpr int TOK_PER_BLOCK   = WARPS_PER_BLOCK * TOK_PER_WARP;  // 32

__global__ __launch_bounds__(WARPS_PER_BLOCK * 32)
void moe_gate_kernel(const float* __restrict__ hs,
                     const float* __restrict__ w,
                     float* __restrict__ out,
                     int n) {
    const int lane = threadIdx.x & 31;
    const int wid  = threadIdx.x >> 5;
    const int tok0 = (blockIdx.x * WARPS_PER_BLOCK + wid) * TOK_PER_WARP;
    if (tok0 >= n) return;

    const float4* __restrict__ W4 = reinterpret_cast<const float4*>(w);
    const float4* __restrict__ H4 =
        reinterpret_cast<const float4*>(hs) + (size_t)tok0 * VEC;

    float acc[TOK_PER_WARP][NEXP];
#pragma unroll
    for (int i = 0; i < TOK_PER_WARP; i++)
#pragma unroll
        for (int e = 0; e < NEXP; e++) acc[i][e] = 0.0f;

    // 8 LDG.128 per iteration, compiler-scheduled.
    //   hidden: __ldcs (evict-first; 335 MB stream must not thrash caches)
    //   weight: __ldg  (read-only, L1-resident 40 KB working set)
    for (int c = lane; c < VEC; c += 32) {
        const float4 w0 = __ldg(&W4[0 * VEC + c]);
        const float4 w1 = __ldg(&W4[1 * VEC + c]);
        const float4 w2 = __ldg(&W4[2 * VEC + c]);
        const float4 w3 = __ldg(&W4[3 * VEC + c]);
#pragma unroll
        for (int i = 0; i < TOK_PER_WARP; i++) {
            const float4 h = __ldcs(&H4[(size_t)i * VEC + c]);
            acc[i][0] = fmaf(h.x, w0.x, fmaf(h.y, w0.y, fmaf(h.z, w0.z, fmaf(h.w, w0.w, acc[i][0]))));
            acc[i][1] = fmaf(h.x, w1.x, fmaf(h.y, w1.y, fmaf(h.z, w1.z, fmaf(h.w, w1.w, acc[i][1]))));
            acc[i][2] = fmaf(h.x, w2.x, fmaf(h.y, w2.y, fmaf(h.z, w2.z, fmaf(h.w, w2.w, acc[i][2]))));
            acc[i][3] = fmaf(h.x, w3.x, fmaf(h.y, w3.y, fmaf(h.z, w3.z, fmaf(h.w, w3.w, acc[i][3]))));
        }
    }

    // Full butterfly reduce: every lane ends with the complete sums.
#pragma unroll
    for (int i = 0; i < TOK_PER_WARP; i++)
#pragma unroll
        for (int e = 0; e < NEXP; e++) {
            float v = acc[i][e];
#pragma unroll
            for (int off = 16; off > 0; off >>= 1)
                v += __shfl_xor_sync(0xFFFFFFFFu, v, off);
            acc[i][e] = v;
        }

    if (lane < TOK_PER_WARP) {
        const int tok = tok0 + lane;
        if (tok < n) {
            float l[NEXP];
#pragma unroll
            for (int e = 0; e < NEXP; e++) l[e] = acc[lane][e];

            // softmax over 4
            float m = l[0];
#pragma unroll
            for (int e = 1; e < NEXP; e++) m = fmaxf(m, l[e]);
            float p[NEXP];
            float s = 0.0f;
#pragma unroll
            for (int e = 0; e < NEXP; e++) { p[e] = expf(l[e] - m); s += p[e]; }
            const float inv = 1.0f / s;
#pragma unroll
            for (int e = 0; e < NEXP; e++) p[e] *= inv;

            // top-2 with lowest-index tie-break (strict >)
            int bi = 0;
            float bv = p[0];
#pragma unroll
            for (int e = 1; e < NEXP; e++)
                if (p[e] > bv) { bv = p[e]; bi = e; }
            int si = -1;
            float sv = -1.0f;
#pragma unroll
            for (int e = 0; e < NEXP; e++) {
                if (e == bi) continue;
                if (p[e] > sv) { sv = p[e]; si = e; }
            }

            const size_t n2 = 2 * (size_t)n;
            out[(size_t)tok * 2 + 0]          = (float)bi;
            out[(size_t)tok * 2 + 1]          = (float)si;
            out[n2 + (size_t)tok * 2 + 0]     = bv;
            out[n2 + (size_t)tok * 2 + 1]     = sv;
            out[2 * n2 + (size_t)tok * 2 + 0] = (float)tok;
            out[2 * n2 + (size_t)tok * 2 + 1] = (float)(n + tok);
        }
    }
}

extern "C" void kernel_launch(void* const* d_in, const int* in_sizes, int n_in,
                              void* d_out, int out_size) {
    const float* hs = (const float*)d_in[0];
    const float* w  = (const float*)d_in[1];
    float* out      = (float*)d_out;

    const int n = in_sizes[0] / EMBED;  // 32768
    const int blocks = (n + TOK_PER_BLOCK - 1) / TOK_PER_BLOCK;  // 1024
    moe_gate_kernel<<<blocks, WARPS_PER_BLOCK * 32>>>(hs, w, out, n);
}